// round 11
// baseline (speedup 1.0000x reference)
#include <cuda_runtime.h>
#include <cstdint>

#define SEQ    8192
#define NH     32
#define NKV    8
#define NHT    (NH + NKV)           // 40
#define HD     128
#define HALF   64
#define QSIZE  (NH * HD)            // 4096 floats = 16 KB
#define KVSIZE (NKV * HD)           // 1024 floats = 4 KB
#define ROW    (QSIZE + 2 * KVSIZE) // 6144 floats = 24 KB
#define ROW_BYTES (ROW * 4)
#define EPSV   1e-6f

#define THREADS 256                 // 8 warps, 5 heads per warp
#define GRID    592                 // 148 SMs x 4 CTAs (48 KB dyn smem each)
#define DYN_SMEM (2 * ROW_BYTES)    // 49152 B -> needs opt-in (static mbar on top)

__device__ __forceinline__ uint32_t smem_u32(const void* p) {
    return (uint32_t)__cvta_generic_to_shared(p);
}

__device__ __forceinline__ void mbar_wait(uint32_t mbar, uint32_t phase) {
    uint32_t done;
    do {
        asm volatile(
            "{\n\t.reg .pred p;\n\t"
            "mbarrier.try_wait.parity.acquire.cta.shared::cta.b64 p, [%1], %2, 0x989680;\n\t"
            "selp.b32 %0, 1, 0, p;\n\t}"
            : "=r"(done) : "r"(mbar), "r"(phase) : "memory");
    } while (!done);
}

__global__ __launch_bounds__(THREADS)
void qknorm_rope_kernel(const float* __restrict__ qkv,
                        const float* __restrict__ qw,
                        const float* __restrict__ kw,
                        const float* __restrict__ cosw,
                        const float* __restrict__ sinw,
                        float* __restrict__ out)
{
    extern __shared__ __align__(128) float dyn[];   // 2 x 24 KB token buffers
    __shared__ __align__(8) unsigned long long s_mbar[2];

    const int tid  = threadIdx.x;
    const uint32_t mb[2] = { smem_u32(&s_mbar[0]), smem_u32(&s_mbar[1]) };
    const uint32_t sbuf[2] = { smem_u32(dyn), smem_u32(dyn + ROW) };

    if (tid == 0) {
        asm volatile("mbarrier.init.shared::cta.b64 [%0], %1;" :: "r"(mb[0]), "r"(1));
        asm volatile("mbarrier.init.shared::cta.b64 [%0], %1;" :: "r"(mb[1]), "r"(1));
    }
    __syncthreads();

    // Per-lane column constants (hoisted across all tokens).
    const int warp = tid >> 5;
    const int lane = tid & 31;
    const int c    = lane * 2;
    const float2 clo = *reinterpret_cast<const float2*>(cosw + c);
    const float2 chi = *reinterpret_cast<const float2*>(cosw + c + HALF);
    const float2 slo = *reinterpret_cast<const float2*>(sinw + c);
    const float2 shi = *reinterpret_cast<const float2*>(sinw + c + HALF);
    const float2 wql = *reinterpret_cast<const float2*>(qw + c);
    const float2 wqh = *reinterpret_cast<const float2*>(qw + c + HALF);
    const float2 wkl = *reinterpret_cast<const float2*>(kw + c);
    const float2 wkh = *reinterpret_cast<const float2*>(kw + c + HALF);

    // Prologue: load first token into buffer 0.
    const int t0 = blockIdx.x;
    if (tid == 0) {
        asm volatile("mbarrier.arrive.expect_tx.shared::cta.b64 _, [%0], %1;"
                     :: "r"(mb[0]), "r"((uint32_t)ROW_BYTES));
        asm volatile(
            "cp.async.bulk.shared::cta.global.mbarrier::complete_tx::bytes "
            "[%0], [%1], %2, [%3];"
            :: "r"(sbuf[0]), "l"(qkv + (size_t)t0 * ROW),
               "r"((uint32_t)ROW_BYTES), "r"(mb[0]) : "memory");
    }

    int it = 0;
    for (int t = t0; t < SEQ; t += GRID, it++) {
        const int b = it & 1;
        const uint32_t phase = (uint32_t)((it >> 1) & 1);
        float* buf = dyn + b * ROW;

        // Prefetch next token into the other buffer. The previous V bulk
        // store from that buffer must finish reading smem first
        // (wait_group.read 0); compute reads finished at last iteration's
        // __syncthreads.
        const int tn = t + GRID;
        if (tid == 0 && tn < SEQ) {
            asm volatile("cp.async.bulk.wait_group.read 0;" ::: "memory");
            asm volatile("mbarrier.arrive.expect_tx.shared::cta.b64 _, [%0], %1;"
                         :: "r"(mb[b ^ 1]), "r"((uint32_t)ROW_BYTES));
            asm volatile(
                "cp.async.bulk.shared::cta.global.mbarrier::complete_tx::bytes "
                "[%0], [%1], %2, [%3];"
                :: "r"(sbuf[b ^ 1]), "l"(qkv + (size_t)tn * ROW),
                   "r"((uint32_t)ROW_BYTES), "r"(mb[b ^ 1]) : "memory");
        }

        // Wait for current buffer.
        mbar_wait(mb[b], phase);

        // V passthrough: bulk store straight from smem; overlaps compute.
        if (tid == 0) {
            float* vdst = out + (size_t)SEQ * (QSIZE + KVSIZE) + (size_t)t * KVSIZE;
            asm volatile(
                "cp.async.bulk.global.shared::cta.bulk_group [%0], [%1], %2;"
                :: "l"(vdst), "r"(sbuf[b] + (QSIZE + KVSIZE) * 4),
                   "r"((uint32_t)(KVSIZE * 4)) : "memory");
            asm volatile("cp.async.bulk.commit_group;" ::: "memory");
        }

        // Q/K: 8 warps x 5 heads; lane owns rotate_half pair (c, c+64).
        #pragma unroll
        for (int i = 0; i < 5; i++) {
            const int h = warp * 5 + i;            // 0..39
            const float* hs = buf + h * HD;

            float2 xlo = *reinterpret_cast<const float2*>(hs + c);
            float2 xhi = *reinterpret_cast<const float2*>(hs + c + HALF);

            float ss = xlo.x * xlo.x + xlo.y * xlo.y
                     + xhi.x * xhi.x + xhi.y * xhi.y;
            #pragma unroll
            for (int off = 16; off > 0; off >>= 1)
                ss += __shfl_xor_sync(0xffffffffu, ss, off);

            const float inv = rsqrtf(ss * (1.0f / HD) + EPSV);

            const bool isq = (h < NH);
            const float2 wl = isq ? wql : wkl;
            const float2 wh = isq ? wqh : wkh;
            float* dst = isq ? (out + (size_t)t * QSIZE + h * HD)
                             : (out + (size_t)SEQ * QSIZE + (size_t)t * KVSIZE
                                    + (h - NH) * HD);

            const float nl0 = xlo.x * inv * wl.x, nl1 = xlo.y * inv * wl.y;
            const float nh0 = xhi.x * inv * wh.x, nh1 = xhi.y * inv * wh.y;

            float2 olo, ohi;
            olo.x = nl0 * clo.x - nh0 * slo.x;
            olo.y = nl1 * clo.y - nh1 * slo.y;
            ohi.x = nh0 * chi.x + nl0 * shi.x;
            ohi.y = nh1 * chi.y + nl1 * shi.y;

            __stcs(reinterpret_cast<float2*>(dst + c), olo);
            __stcs(reinterpret_cast<float2*>(dst + c + HALF), ohi);
        }

        // All threads done reading buf before it is reloaded at it+2.
        __syncthreads();
    }

    // Fully drain pending V bulk stores before the CTA exits.
    if (tid == 0) {
        asm volatile("cp.async.bulk.wait_group 0;" ::: "memory");
    }
    __syncthreads();
}

extern "C" void kernel_launch(void* const* d_in, const int* in_sizes, int n_in,
                              void* d_out, int out_size)
{
    const float* qkv  = (const float*)d_in[0];
    const float* qw   = (const float*)d_in[1];
    const float* kw   = (const float*)d_in[2];
    const float* cosw = (const float*)d_in[3];
    const float* sinw = (const float*)d_in[4];
    float* out = (float*)d_out;

    // Opt-in: 48 KB dynamic + 16 B static mbarriers exceeds the default
    // 48 KB per-block cap. Idempotent, not a stream op -> capture-safe.
    cudaFuncSetAttribute(qknorm_rope_kernel,
                         cudaFuncAttributeMaxDynamicSharedMemorySize,
                         DYN_SMEM + 1024);

    qknorm_rope_kernel<<<GRID, THREADS, DYN_SMEM>>>(qkv, qw, kw, cosw, sinw, out);
}

// round 12
// speedup vs baseline: 1.1912x; 1.1912x over previous
#include <cuda_runtime.h>

#define SEQ    8192
#define NH     32
#define NKV    8
#define NHT    (NH + NKV)           // 40 heads per token
#define HD     128
#define HALF   64
#define QSIZE  (NH * HD)            // 4096
#define KVSIZE (NKV * HD)           // 1024
#define ROW    (QSIZE + 2 * KVSIZE) // 6144
#define EPSV   1e-6f

#define WARPS_PER_BLOCK 8
#define THREADS 256
#define TASKS_PER_WARP 2            // each task = 2 head-rows (lane-split)

// QK rows: SEQ*NHT = 327680. 4 rows per warp -> 81920 warp-groups -> /8 = 10240 blocks
#define QK_WARPJOBS ((SEQ * NHT) / (2 * TASKS_PER_WARP))
#define QK_BLOCKS   (QK_WARPJOBS / WARPS_PER_BLOCK)
// V copy: SEQ*KVSIZE/4 float4 = 2097152; 2 per thread -> /512 = 4096 blocks
#define V_FLOAT4  ((SEQ * KVSIZE) / 4)
#define V_BLOCKS  (V_FLOAT4 / (THREADS * 2))

__global__ __launch_bounds__(THREADS)
void qknorm_rope_kernel(const float* __restrict__ qkv,
                        const float* __restrict__ qw,
                        const float* __restrict__ kw,
                        const float* __restrict__ cosw,
                        const float* __restrict__ sinw,
                        float* __restrict__ out)
{
    if (blockIdx.x < QK_BLOCKS) {
        const int warp = threadIdx.x >> 5;
        const int lane = threadIdx.x & 31;
        const int job  = blockIdx.x * WARPS_PER_BLOCK + warp;
        const int rbase = job * (2 * TASKS_PER_WARP);   // first of 4 rows
        const int lh   = lane >> 4;                     // 0 or 1: which row of a task
        const int c    = (lane & 15) * 4;               // column within lo half

        const float* src[TASKS_PER_WARP];
        float*       dst[TASKS_PER_WARP];
        const float* w[TASKS_PER_WARP];

        #pragma unroll
        for (int t = 0; t < TASKS_PER_WARP; t++) {
            const int row = rbase + t * 2 + lh;
            const int s = row / NHT;
            const int h = row - s * NHT;
            if (h < NH) {
                src[t] = qkv + (size_t)s * ROW + h * HD;
                dst[t] = out + (size_t)s * QSIZE + h * HD;
                w[t]   = qw;
            } else {
                const int kh = h - NH;
                src[t] = qkv + (size_t)s * ROW + QSIZE + kh * HD;
                dst[t] = out + (size_t)SEQ * QSIZE + (size_t)s * KVSIZE + kh * HD;
                w[t]   = kw;
            }
        }

        // 4 independent streaming loads issued back-to-back (MLP_p1 = 4).
        float4 xlo[TASKS_PER_WARP], xhi[TASKS_PER_WARP];
        #pragma unroll
        for (int t = 0; t < TASKS_PER_WARP; t++) {
            xlo[t] = __ldcs(reinterpret_cast<const float4*>(src[t] + c));
            xhi[t] = __ldcs(reinterpret_cast<const float4*>(src[t] + c + HALF));
        }

        float ss[TASKS_PER_WARP];
        #pragma unroll
        for (int t = 0; t < TASKS_PER_WARP; t++)
            ss[t] = xlo[t].x * xlo[t].x + xlo[t].y * xlo[t].y
                  + xlo[t].z * xlo[t].z + xlo[t].w * xlo[t].w
                  + xhi[t].x * xhi[t].x + xhi[t].y * xhi[t].y
                  + xhi[t].z * xhi[t].z + xhi[t].w * xhi[t].w;

        // Interleaved 16-lane butterfly reductions (both tasks pipeline).
        #pragma unroll
        for (int off = 8; off > 0; off >>= 1) {
            #pragma unroll
            for (int t = 0; t < TASKS_PER_WARP; t++)
                ss[t] += __shfl_xor_sync(0xffffffffu, ss[t], off);
        }

        const float4 clo = *reinterpret_cast<const float4*>(cosw + c);
        const float4 chi = *reinterpret_cast<const float4*>(cosw + c + HALF);
        const float4 slo = *reinterpret_cast<const float4*>(sinw + c);
        const float4 shi = *reinterpret_cast<const float4*>(sinw + c + HALF);

        #pragma unroll
        for (int t = 0; t < TASKS_PER_WARP; t++) {
            const float inv = rsqrtf(ss[t] * (1.0f / HD) + EPSV);

            const float4 wl = *reinterpret_cast<const float4*>(w[t] + c);
            const float4 wh = *reinterpret_cast<const float4*>(w[t] + c + HALF);

            const float nl0 = xlo[t].x * inv * wl.x, nl1 = xlo[t].y * inv * wl.y;
            const float nl2 = xlo[t].z * inv * wl.z, nl3 = xlo[t].w * inv * wl.w;
            const float nh0 = xhi[t].x * inv * wh.x, nh1 = xhi[t].y * inv * wh.y;
            const float nh2 = xhi[t].z * inv * wh.z, nh3 = xhi[t].w * inv * wh.w;

            float4 olo, ohi;
            olo.x = nl0 * clo.x - nh0 * slo.x;
            olo.y = nl1 * clo.y - nh1 * slo.y;
            olo.z = nl2 * clo.z - nh2 * slo.z;
            olo.w = nl3 * clo.w - nh3 * slo.w;
            ohi.x = nh0 * chi.x + nl0 * shi.x;
            ohi.y = nh1 * chi.y + nl1 * shi.y;
            ohi.z = nh2 * chi.z + nl2 * shi.z;
            ohi.w = nh3 * chi.w + nl3 * shi.w;

            __stcs(reinterpret_cast<float4*>(dst[t] + c), olo);
            __stcs(reinterpret_cast<float4*>(dst[t] + c + HALF), ohi);
        }
    } else {
        // V passthrough: 2 float4 per thread, streaming hints.
        const int vblock = blockIdx.x - QK_BLOCKS;
        const int i0 = vblock * (THREADS * 2) + threadIdx.x;
        const int i1 = i0 + THREADS;
        const float* vbase = qkv + QSIZE + KVSIZE;
        float* vout = out + (size_t)SEQ * (QSIZE + KVSIZE);

        const int s0 = i0 >> 8, c0 = i0 & 255;   // 256 float4 per row
        const int s1 = i1 >> 8, c1 = i1 & 255;

        float4 v0 = __ldcs(reinterpret_cast<const float4*>(vbase + (size_t)s0 * ROW) + c0);
        float4 v1 = __ldcs(reinterpret_cast<const float4*>(vbase + (size_t)s1 * ROW) + c1);
        __stcs(reinterpret_cast<float4*>(vout) + i0, v0);
        __stcs(reinterpret_cast<float4*>(vout) + i1, v1);
    }
}

extern "C" void kernel_launch(void* const* d_in, const int* in_sizes, int n_in,
                              void* d_out, int out_size)
{
    const float* qkv  = (const float*)d_in[0];
    const float* qw   = (const float*)d_in[1];
    const float* kw   = (const float*)d_in[2];
    const float* cosw = (const float*)d_in[3];
    const float* sinw = (const float*)d_in[4];
    float* out = (float*)d_out;

    qknorm_rope_kernel<<<QK_BLOCKS + V_BLOCKS, THREADS>>>(qkv, qw, kw, cosw, sinw, out);
}